// round 15
// baseline (speedup 1.0000x reference)
#include <cuda_runtime.h>
#include <cuda_bf16.h>
#include <stdint.h>

#define BATCH 4
#define SEQ   2048
#define EMBD  1024
#define NH    16
#define DKH   64
#define BH    64
#define BSQ   8192
#define QKV_ELEMS  (BATCH * NH * SEQ * DKH)
#define PRED_ELEMS (BSQ * EMBD)
#define ATTN_ELEMS ((size_t)BH * SEQ * SEQ)

__device__ float  g_attn_fb[ATTN_ELEMS];   // reused as bf16 hi | lo planes
__device__ int    g_mask_mode;
__device__ __nv_bfloat16 g_inh[3u * QKV_ELEMS], g_inl[3u * QKV_ELEMS];
__device__ __nv_bfloat16 g_wth[4u * EMBD * EMBD], g_wtl[4u * EMBD * EMBD];
__device__ __nv_bfloat16 g_qh[QKV_ELEMS], g_ql[QKV_ELEMS];
__device__ __nv_bfloat16 g_kh[QKV_ELEMS], g_kl[QKV_ELEMS];
__device__ __nv_bfloat16 g_vh[QKV_ELEMS], g_vl[QKV_ELEMS];
__device__ __nv_bfloat16 g_ph[PRED_ELEMS], g_pl[PRED_ELEMS];

#define OF_AH  1024u
#define OF_AL  (1024u + 16384u)
#define OF_BH  (1024u + 32768u)
#define OF_BL  (1024u + 49152u)
#define SMEM_BYTES (1024 + 4 * 16384)
#define ONES2  0x3F803F80u

__device__ __forceinline__ uint32_t smem_u32(const void* p) {
    uint32_t a;
    asm("{ .reg .u64 t; cvta.to.shared.u64 t, %1; cvt.u32.u64 %0, t; }" : "=r"(a) : "l"(p));
    return a;
}
__device__ __forceinline__ void split_bf(float x, __nv_bfloat16& h, __nv_bfloat16& l) {
    h = __float2bfloat16(x);
    l = __float2bfloat16(x - __bfloat162float(h));
}
__device__ __forceinline__ uint32_t pack2(__nv_bfloat16 a, __nv_bfloat16 b) {
    return (uint32_t)__bfloat16_as_ushort(a) | ((uint32_t)__bfloat16_as_ushort(b) << 16);
}
__device__ __forceinline__ void mma16816(float* d, const uint32_t* a, uint32_t b0, uint32_t b1) {
    asm volatile("mma.sync.aligned.m16n8k16.row.col.f32.bf16.bf16.f32 "
                 "{%0,%1,%2,%3}, {%4,%5,%6,%7}, {%8,%9}, {%0,%1,%2,%3};"
                 : "+f"(d[0]), "+f"(d[1]), "+f"(d[2]), "+f"(d[3])
                 : "r"(a[0]), "r"(a[1]), "r"(a[2]), "r"(a[3]), "r"(b0), "r"(b1));
}
__device__ __forceinline__ void ldsm4(uint32_t* r, uint32_t a) {
    asm volatile("ldmatrix.sync.aligned.m8n8.x4.shared.b16 {%0,%1,%2,%3}, [%4];"
                 : "=r"(r[0]), "=r"(r[1]), "=r"(r[2]), "=r"(r[3]) : "r"(a));
}
__device__ __forceinline__ void ldsm4t(uint32_t* r, uint32_t a) {
    asm volatile("ldmatrix.sync.aligned.m8n8.x4.trans.shared.b16 {%0,%1,%2,%3}, [%4];"
                 : "=r"(r[0]), "=r"(r[1]), "=r"(r[2]), "=r"(r[3]) : "r"(a));
}
__device__ __forceinline__ void cp16(uint32_t d, const void* s) {
    asm volatile("cp.async.cg.shared.global [%0], [%1], 16;" :: "r"(d), "l"(s));
}
#define CP_COMMIT() asm volatile("cp.async.commit_group;" ::: "memory")
#define CP_WAIT(n)  asm volatile("cp.async.wait_group %0;" :: "n"(n) : "memory")

// bf16 [128 x 32] K-slab -> col-half `st` of swizzled tile.
__device__ __forceinline__ void cpa(const __nv_bfloat16* __restrict__ s, int ld, uint32_t db,
                                    int st, int tid) {
    for (int i = tid; i < 512; i += 256) {
        const int r = i >> 2, q = i & 3, c = st * 4 + q;
        cp16(db + r * 128 + ((c ^ (r & 7)) << 4), s + (size_t)r * ld + q * 8);
    }
}
// bf16 [32 x 64] k-rows slab (av B): stage occupies row range.
__device__ __forceinline__ void cpb(const __nv_bfloat16* __restrict__ s, uint32_t db,
                                    int st, int tid) {
    if (tid < 256) {
        const int r = tid >> 3, q = tid & 7, pr = st * 32 + r;
        cp16(db + pr * 128 + ((q ^ (pr & 7)) << 4), s + (size_t)r * DKH + q * 8);
    }
}

// One K=32 stage. Optional deterministic row-sums via ones-matrix MMA (TRB path).
template<int NB, bool TRB>
__device__ __forceinline__ void stage_mma(uint32_t sb, int s, int wid, int lane, float* acc,
                                          float* sums, int do_sums) {
    constexpr int NA = NB / 16;
    const int wm = (wid >> 1) * 32, wn = (wid & 1) * (NB / 2);
    const int l15 = lane & 15, lh = lane >> 4;
    #pragma unroll
    for (int kk = 0; kk < 2; ++kk) {
        uint32_t ah[2][4], al[2][4];
        const int ca = s * 4 + kk * 2 + lh;
        #pragma unroll
        for (int im = 0; im < 2; ++im) {
            const int r = wm + im * 16 + l15;
            const uint32_t sw = r * 128 + ((ca ^ (r & 7)) << 4);
            ldsm4(ah[im], sb + OF_AH + sw);
            ldsm4(al[im], sb + OF_AL + sw);
        }
        if (TRB && do_sums) {
            #pragma unroll
            for (int im = 0; im < 2; ++im) {
                mma16816(sums + im * 4, ah[im], ONES2, ONES2);
                mma16816(sums + im * 4, al[im], ONES2, ONES2);
            }
        }
        #pragma unroll
        for (int ap = 0; ap < NA / 2; ++ap) {
            uint32_t bh[4], bl[4];
            if (!TRB) {
                const int r = wn + ap * 16 + l15;
                const uint32_t sw = r * 128 + ((ca ^ (r & 7)) << 4);
                ldsm4(bh, sb + OF_BH + sw);
                ldsm4(bl, sb + OF_BL + sw);
                #pragma unroll
                for (int im = 0; im < 2; ++im) {
                    float* d0 = acc + (im * NA + ap * 2) * 4;
                    float* d1 = acc + (im * NA + ap * 2 + 1) * 4;
                    mma16816(d0, ah[im], bh[0], bh[2]);
                    mma16816(d1, ah[im], bh[1], bh[3]);
                    mma16816(d0, ah[im], bl[0], bl[2]);
                    mma16816(d1, ah[im], bl[1], bl[3]);
                    mma16816(d0, al[im], bh[0], bh[2]);
                    mma16816(d1, al[im], bh[1], bh[3]);
                }
            } else {
                const int r = s * 32 + kk * 16 + l15, c = ((wn + ap * 16) >> 3) + lh;
                const uint32_t sw = r * 128 + ((c ^ (r & 7)) << 4);
                ldsm4t(bh, sb + OF_BH + sw);
                ldsm4t(bl, sb + OF_BL + sw);
                #pragma unroll
                for (int im = 0; im < 2; ++im) {
                    float* d0 = acc + (im * NA + ap * 2) * 4;
                    float* d1 = acc + (im * NA + ap * 2 + 1) * 4;
                    mma16816(d0, ah[im], bh[0], bh[1]);
                    mma16816(d1, ah[im], bh[2], bh[3]);
                    mma16816(d0, ah[im], bl[0], bl[1]);
                    mma16816(d1, ah[im], bl[2], bl[3]);
                    mma16816(d0, al[im], bh[0], bh[1]);
                    mma16816(d1, al[im], bh[2], bh[3]);
                }
            }
        }
    }
}

__global__ void detect_mask_kernel(const unsigned int* __restrict__ m) {
    __shared__ int s01, sf;
    if (threadIdx.x == 0) { s01 = 1; sf = 1; }
    __syncthreads();
    int a01 = 1, af = 1;
    for (int i = threadIdx.x; i < 65536; i += blockDim.x) {
        const unsigned int w = m[i];
        if (w > 1u) a01 = 0;
        if (w != 0u && w != 0x3f800000u) af = 0;
    }
    if (!a01) atomicAnd(&s01, 0);
    if (!af)  atomicAnd(&sf, 0);
    __syncthreads();
    if (threadIdx.x == 0) g_mask_mode = s01 ? 1 : (sf ? 2 : 0);
}

__global__ __launch_bounds__(256) void convert_in_kernel(
    const float* __restrict__ Q, const float* __restrict__ K, const float* __restrict__ V) {
    const int z = blockIdx.z;
    const float* s = (z == 0) ? Q : (z == 1) ? K : V;
    const size_t i = ((size_t)blockIdx.x * 256 + threadIdx.x) * 4;
    const float4 v = *(const float4*)(s + i);
    __nv_bfloat16 h0, h1, h2, h3, l0, l1, l2, l3;
    split_bf(v.x, h0, l0); split_bf(v.y, h1, l1); split_bf(v.z, h2, l2); split_bf(v.w, h3, l3);
    const size_t o = (size_t)z * QKV_ELEMS + i;
    *(uint2*)(g_inh + o) = make_uint2(pack2(h0, h1), pack2(h2, h3));
    *(uint2*)(g_inl + o) = make_uint2(pack2(l0, l1), pack2(l2, l3));
}

__global__ __launch_bounds__(256) void convert_w_kernel(
    const float* __restrict__ WQ, const float* __restrict__ WK,
    const float* __restrict__ WV, const float* __restrict__ Wfc) {
    const int z = blockIdx.z;
    const float* W = (z == 0) ? WQ : (z == 1) ? WK : (z == 2) ? WV : Wfc;
    __shared__ float t[32][33];
    const int tx = threadIdx.x & 31, ty = threadIdx.x >> 5;
    const int x0 = blockIdx.x * 32, y0 = blockIdx.y * 32;
    #pragma unroll
    for (int j = 0; j < 4; ++j)
        t[ty + j * 8][tx] = W[(size_t)(y0 + ty + j * 8) * EMBD + x0 + tx];
    __syncthreads();
    __nv_bfloat16* dh = g_wth + (size_t)z * EMBD * EMBD;
    __nv_bfloat16* dl = g_wtl + (size_t)z * EMBD * EMBD;
    #pragma unroll
    for (int j = 0; j < 4; ++j) {
        __nv_bfloat16 hh, ll;
        split_bf(t[tx][ty + j * 8], hh, ll);
        const size_t o = (size_t)(x0 + ty + j * 8) * EMBD + y0 + tx;
        dh[o] = hh; dl[o] = ll;
    }
}

// attn f32 (normalized) -> hi/lo planes; attn-output path only.
__global__ __launch_bounds__(256) void convert_attn_kernel(
    const float* __restrict__ a, __nv_bfloat16* __restrict__ hi, __nv_bfloat16* __restrict__ lo) {
    const size_t i = ((size_t)blockIdx.x * 256 + threadIdx.x) * 4;
    const float4 v = *(const float4*)(a + i);
    __nv_bfloat16 h0, h1, h2, h3, l0, l1, l2, l3;
    split_bf(v.x, h0, l0); split_bf(v.y, h1, l1); split_bf(v.z, h2, l2); split_bf(v.w, h3, l3);
    *(uint2*)(hi + i) = make_uint2(pack2(h0, h1), pack2(h2, h3));
    *(uint2*)(lo + i) = make_uint2(pack2(l0, l1), pack2(l2, l3));
}

// QKV projection: 128x128 tiles, 32 pipelined K=32 stages.
__global__ __launch_bounds__(256, 2) void proj_gemm(void) {
    extern __shared__ unsigned char smem[];
    const uint32_t sb = smem_u32(smem);
    const int tid = threadIdx.x, wid = tid >> 5, lane = tid & 31;
    const int z = blockIdx.z, m0 = blockIdx.y * 128, n0 = blockIdx.x * 128;
    const __nv_bfloat16* Ah = g_inh + (size_t)z * QKV_ELEMS + (size_t)m0 * EMBD;
    const __nv_bfloat16* Al = g_inl + (size_t)z * QKV_ELEMS + (size_t)m0 * EMBD;
    const __nv_bfloat16* Bh = g_wth + (size_t)z * EMBD * EMBD + (size_t)n0 * EMBD;
    const __nv_bfloat16* Bl = g_wtl + (size_t)z * EMBD * EMBD + (size_t)n0 * EMBD;
    float acc[64] = {};
    cpa(Ah, EMBD, sb + OF_AH, 0, tid); cpa(Al, EMBD, sb + OF_AL, 0, tid);
    cpa(Bh, EMBD, sb + OF_BH, 0, tid); cpa(Bl, EMBD, sb + OF_BL, 0, tid);
    CP_COMMIT();
    for (int c = 0; c < 32; ++c) {
        if (c < 31) {
            const int k = (c + 1) * 32, s = (c + 1) & 1;
            cpa(Ah + k, EMBD, sb + OF_AH, s, tid); cpa(Al + k, EMBD, sb + OF_AL, s, tid);
            cpa(Bh + k, EMBD, sb + OF_BH, s, tid); cpa(Bl + k, EMBD, sb + OF_BL, s, tid);
            CP_COMMIT(); CP_WAIT(1);
        } else CP_WAIT(0);
        __syncthreads();
        stage_mma<128, false>(sb, c & 1, wid, lane, acc, nullptr, 0);
        __syncthreads();
    }
    const int gid = lane >> 2, t4 = lane & 3, wm = (wid >> 1) * 32, wn = (wid & 1) * 64;
    __nv_bfloat16* dh = (z == 0) ? g_qh : (z == 1) ? g_kh : g_vh;
    __nv_bfloat16* dl = (z == 0) ? g_ql : (z == 1) ? g_kl : g_vl;
    #pragma unroll
    for (int im = 0; im < 2; ++im)
        #pragma unroll
        for (int ia = 0; ia < 8; ++ia) {
            const float* cc = acc + (im * 8 + ia) * 4;
            const int n = n0 + wn + ia * 8 + t4 * 2, h = n >> 6, d = n & 63;
            #pragma unroll
            for (int hr = 0; hr < 2; ++hr) {
                const int m = m0 + wm + im * 16 + gid + hr * 8;
                const int b = m >> 11, s = m & (SEQ - 1);
                __nv_bfloat16 p0, p1, q0, q1;
                split_bf(cc[hr * 2 + 0], p0, q0);
                split_bf(cc[hr * 2 + 1], p1, q1);
                const size_t o = (((size_t)(b * NH + h)) * SEQ + s) * DKH + d;
                *(uint32_t*)(dh + o) = pack2(p0, p1);
                *(uint32_t*)(dl + o) = pack2(q0, q1);
            }
        }
}

// scores: per (b,h) 128x128 tile, K=64.
// expout=1: write p=exp(s/8) (0 if masked) as bf16 hi/lo planes.
// expout=0: write masked raw f32 scores (attn-output path).
__global__ __launch_bounds__(256, 2) void scores_gemm(
    const void* __restrict__ mask, float* __restrict__ attn,
    __nv_bfloat16* __restrict__ phi, __nv_bfloat16* __restrict__ plo, int expout) {
    extern __shared__ unsigned char smem[];
    const uint32_t sb = smem_u32(smem);
    const int tid = threadIdx.x, wid = tid >> 5, lane = tid & 31;
    const int z = blockIdx.z, b = z >> 4;
    const int m0 = blockIdx.y * 128, n0 = blockIdx.x * 128;
    const size_t zo = (size_t)z * SEQ * DKH;
    const __nv_bfloat16* qh = g_qh + zo + (size_t)m0 * DKH;
    const __nv_bfloat16* ql = g_ql + zo + (size_t)m0 * DKH;
    const __nv_bfloat16* kh = g_kh + zo + (size_t)n0 * DKH;
    const __nv_bfloat16* kl = g_kl + zo + (size_t)n0 * DKH;
    #pragma unroll
    for (int s = 0; s < 2; ++s) {
        cpa(qh + s * 32, DKH, sb + OF_AH, s, tid); cpa(ql + s * 32, DKH, sb + OF_AL, s, tid);
        cpa(kh + s * 32, DKH, sb + OF_BH, s, tid); cpa(kl + s * 32, DKH, sb + OF_BL, s, tid);
    }
    CP_COMMIT(); CP_WAIT(0);
    __syncthreads();
    float acc[64] = {};
    stage_mma<128, false>(sb, 0, wid, lane, acc, nullptr, 0);
    stage_mma<128, false>(sb, 1, wid, lane, acc, nullptr, 0);
    __syncthreads();
    {
        const int mode = g_mask_mode;
        for (int i = tid; i < 128 * 32; i += 256) {
            const int r = i >> 5, c0 = (i & 31) * 4;
            const size_t g = ((size_t)b * SEQ + m0 + r) * SEQ + n0 + c0;
            uint32_t f4;
            if (mode == 1) {
                const int4 w = *(const int4*)((const int*)mask + g);
                f4 = (w.x?1u:0u) | ((w.y?1u:0u)<<8) | ((w.z?1u:0u)<<16) | ((w.w?1u:0u)<<24);
            } else if (mode == 2) {
                const float4 w = *(const float4*)((const float*)mask + g);
                f4 = (w.x!=0.f?1u:0u) | ((w.y!=0.f?1u:0u)<<8) | ((w.z!=0.f?1u:0u)<<16) | ((w.w!=0.f?1u:0u)<<24);
            } else {
                f4 = *(const uint32_t*)((const unsigned char*)mask + g);
            }
            *(uint32_t*)(smem + OF_AH + r * 132 + c0) = f4;
        }
    }
    __syncthreads();
    const int gid = lane >> 2, t4 = lane & 3, wm = (wid >> 1) * 32, wn = (wid & 1) * 64;
    #pragma unroll
    for (int im = 0; im < 2; ++im)
        #pragma unroll
        for (int ia = 0; ia < 8; ++ia) {
            const float* cc = acc + (im * 8 + ia) * 4;
            const int ln = wn + ia * 8 + t4 * 2;
            #pragma unroll
            for (int hr = 0; hr < 2; ++hr) {
                const int rl = wm + im * 16 + gid + hr * 8;
                const unsigned char* fr = smem + OF_AH + rl * 132 + ln;
                const size_t go = ((size_t)z * SEQ + m0 + rl) * SEQ + n0 + ln;
                if (expout) {
                    const float p0 = fr[0] ? 0.f : __expf(cc[hr * 2 + 0] * 0.125f);
                    const float p1 = fr[1] ? 0.f : __expf(cc[hr * 2 + 1] * 0.125f);
                    __nv_bfloat16 h0, h1, l0, l1;
                    split_bf(p0, h0, l0); split_bf(p1, h1, l1);
                    *(uint32_t*)(phi + go) = pack2(h0, h1);
                    *(uint32_t*)(plo + go) = pack2(l0, l1);
                } else {
                    float2 o;
                    o.x = fr[0] ? -1e9f : cc[hr * 2 + 0] * 0.125f;
                    o.y = fr[1] ? -1e9f : cc[hr * 2 + 1] * 0.125f;
                    *(float2*)(attn + go) = o;
                }
            }
        }
}

__global__ __launch_bounds__(256) void softmax_kernel(float* __restrict__ attn) {
    float* p = attn + (size_t)blockIdx.x * SEQ;
    const int t = threadIdx.x;
    float v[8], m = -3.4e38f;
    #pragma unroll
    for (int j = 0; j < 8; ++j) { v[j] = p[t + j * 256]; m = fmaxf(m, v[j]); }
    __shared__ float red[8]; __shared__ float bmax, bsum;
    #pragma unroll
    for (int o = 16; o > 0; o >>= 1) m = fmaxf(m, __shfl_xor_sync(0xffffffffu, m, o));
    if ((t & 31) == 0) red[t >> 5] = m;
    __syncthreads();
    if (t == 0) {
        float mm = red[0];
        #pragma unroll
        for (int i = 1; i < 8; ++i) mm = fmaxf(mm, red[i]);
        bmax = mm;
    }
    __syncthreads();
    m = bmax;
    float s = 0.f;
    #pragma unroll
    for (int j = 0; j < 8; ++j) { v[j] = __expf(v[j] - m); s += v[j]; }
    __syncthreads();
    #pragma unroll
    for (int o = 16; o > 0; o >>= 1) s += __shfl_xor_sync(0xffffffffu, s, o);
    if ((t & 31) == 0) red[t >> 5] = s;
    __syncthreads();
    if (t == 0) {
        float ss = red[0];
        #pragma unroll
        for (int i = 1; i < 8; ++i) ss += red[i];
        bsum = ss;
    }
    __syncthreads();
    const float inv = 1.0f / bsum;
    #pragma unroll
    for (int j = 0; j < 8; ++j) p[t + j * 256] = v[j] * inv;
}

// av: per (b,h) M=2048 N=64 K=2048; pure cp.async bf16 GEMM, 64 stages.
// scaled=1: A holds unnormalized p; row sums accumulated via ones-MMA, acc /= sum.
__global__ __launch_bounds__(256, 2) void av_gemm(
    const __nv_bfloat16* __restrict__ pah, const __nv_bfloat16* __restrict__ pal, int scaled) {
    extern __shared__ unsigned char smem[];
    const uint32_t sb = smem_u32(smem);
    const int tid = threadIdx.x, wid = tid >> 5, lane = tid & 31;
    const int z = blockIdx.z, b = z >> 4, h = z & 15, m0 = blockIdx.y * 128;
    const size_t zo = (size_t)z * SEQ * DKH;
    const __nv_bfloat16* Ah = pah + (size_t)z * SEQ * SEQ + (size_t)m0 * SEQ;
    const __nv_bfloat16* Al = pal + (size_t)z * SEQ * SEQ + (size_t)m0 * SEQ;
    float acc[32] = {}, sums[8] = {};
    cpa(Ah, SEQ, sb + OF_AH, 0, tid); cpa(Al, SEQ, sb + OF_AL, 0, tid);
    cpb(g_vh + zo, sb + OF_BH, 0, tid); cpb(g_vl + zo, sb + OF_BL, 0, tid);
    CP_COMMIT();
    for (int c = 0; c < 64; ++c) {
        if (c < 63) {
            const int k = (c + 1) * 32, s = (c + 1) & 1;
            cpa(Ah + k, SEQ, sb + OF_AH, s, tid); cpa(Al + k, SEQ, sb + OF_AL, s, tid);
            cpb(g_vh + zo + (size_t)k * DKH, sb + OF_BH, s, tid);
            cpb(g_vl + zo + (size_t)k * DKH, sb + OF_BL, s, tid);
            CP_COMMIT(); CP_WAIT(1);
        } else CP_WAIT(0);
        __syncthreads();
        stage_mma<64, true>(sb, c & 1, wid, lane, acc, sums, scaled);
        __syncthreads();
    }
    const int gid = lane >> 2, t4 = lane & 3, wm = (wid >> 1) * 32, wn = (wid & 1) * 32;
    #pragma unroll
    for (int im = 0; im < 2; ++im)
        #pragma unroll
        for (int ia = 0; ia < 4; ++ia) {
            const float* cc = acc + (im * 4 + ia) * 4;
            const int d = wn + ia * 8 + t4 * 2;
            #pragma unroll
            for (int hr = 0; hr < 2; ++hr) {
                const int m = m0 + wm + im * 16 + gid + hr * 8;
                const float inv = scaled ? 1.0f / sums[im * 4 + hr * 2] : 1.0f;
                __nv_bfloat16 p0, p1, q0, q1;
                split_bf(cc[hr * 2 + 0] * inv, p0, q0);
                split_bf(cc[hr * 2 + 1] * inv, p1, q1);
                const size_t o = ((size_t)(b * SEQ + m)) * EMBD + h * 64 + d;
                *(uint32_t*)(g_ph + o) = pack2(p0, p1);
                *(uint32_t*)(g_pl + o) = pack2(q0, q1);
            }
        }
}

// fc: out = pred @ Wfc, 128x128 tiles, 32 pipelined stages, f32 output.
__global__ __launch_bounds__(256, 2) void fc_gemm(float* __restrict__ out) {
    extern __shared__ unsigned char smem[];
    const uint32_t sb = smem_u32(smem);
    const int tid = threadIdx.x, wid = tid >> 5, lane = tid & 31;
    const int m0 = blockIdx.y * 128, n0 = blockIdx.x * 128;
    const __nv_bfloat16* Ah = g_ph + (size_t)m0 * EMBD;
    const __nv_bfloat16* Al = g_pl + (size_t)m0 * EMBD;
    const __nv_bfloat16* Bh = g_wth + (size_t)3 * EMBD * EMBD + (size_t)n0 * EMBD;
    const __nv_bfloat16* Bl = g_wtl + (size_t)3 * EMBD * EMBD + (size_t)n0 * EMBD;
    float acc[64] = {};
    cpa(Ah, EMBD, sb + OF_AH, 0, tid); cpa(Al, EMBD, sb + OF_AL, 0, tid);
    cpa(Bh, EMBD, sb + OF_BH, 0, tid); cpa(Bl, EMBD, sb + OF_BL, 0, tid);
    CP_COMMIT();
    for (int c = 0; c < 32; ++c) {
        if (c < 31) {
            const int k = (c + 1) * 32, s = (c + 1) & 1;
            cpa(Ah + k, EMBD, sb + OF_AH, s, tid); cpa(Al + k, EMBD, sb + OF_AL, s, tid);
            cpa(Bh + k, EMBD, sb + OF_BH, s, tid); cpa(Bl + k, EMBD, sb + OF_BL, s, tid);
            CP_COMMIT(); CP_WAIT(1);
        } else CP_WAIT(0);
        __syncthreads();
        stage_mma<128, false>(sb, c & 1, wid, lane, acc, nullptr, 0);
        __syncthreads();
    }
    const int gid = lane >> 2, t4 = lane & 3, wm = (wid >> 1) * 32, wn = (wid & 1) * 64;
    #pragma unroll
    for (int im = 0; im < 2; ++im)
        #pragma unroll
        for (int ia = 0; ia < 8; ++ia) {
            const float* cc = acc + (im * 8 + ia) * 4;
            const int n = n0 + wn + ia * 8 + t4 * 2;
            #pragma unroll
            for (int hr = 0; hr < 2; ++hr) {
                const int m = m0 + wm + im * 16 + gid + hr * 8;
                *(float2*)(out + (size_t)m * EMBD + n) =
                    make_float2(cc[hr * 2 + 0], cc[hr * 2 + 1]);
            }
        }
}

extern "C" void kernel_launch(void* const* d_in, const int* in_sizes, int n_in,
                              void* d_out, int out_size) {
    const float* Q = (const float*)d_in[0];
    const float* K = (const float*)d_in[1];
    const float* V = (const float*)d_in[2];
    const void* mask = d_in[3];
    const float* WQ = (const float*)d_in[4];
    const float* WK = (const float*)d_in[5];
    const float* WV = (const float*)d_in[6];
    const float* Wfc = (const float*)d_in[7];
    float* out = (float*)d_out;

    const int attn_out = (out_size >= (int)(PRED_ELEMS + ATTN_ELEMS));
    void* p = nullptr;
    cudaGetSymbolAddress(&p, g_attn_fb);
    __nv_bfloat16* phi = (__nv_bfloat16*)p;
    __nv_bfloat16* plo = phi + ATTN_ELEMS;
    float* attn_ptr = attn_out ? (out + PRED_ELEMS) : (float*)p;

    cudaFuncSetAttribute(proj_gemm,   cudaFuncAttributeMaxDynamicSharedMemorySize, SMEM_BYTES);
    cudaFuncSetAttribute(scores_gemm, cudaFuncAttributeMaxDynamicSharedMemorySize, SMEM_BYTES);
    cudaFuncSetAttribute(av_gemm,     cudaFuncAttributeMaxDynamicSharedMemorySize, SMEM_BYTES);
    cudaFuncSetAttribute(fc_gemm,     cudaFuncAttributeMaxDynamicSharedMemorySize, SMEM_BYTES);

    detect_mask_kernel<<<1, 1024>>>((const unsigned int*)mask);
    convert_in_kernel<<<dim3(QKV_ELEMS / 1024, 1, 3), 256>>>(Q, K, V);
    convert_w_kernel<<<dim3(32, 32, 4), 256>>>(WQ, WK, WV, Wfc);
    proj_gemm<<<dim3(8, 64, 3), 256, SMEM_BYTES>>>();
    if (attn_out) {
        scores_gemm<<<dim3(16, 16, BH), 256, SMEM_BYTES>>>(mask, attn_ptr, phi, plo, 0);
        softmax_kernel<<<BH * SEQ, 256>>>(attn_ptr);
        convert_attn_kernel<<<(unsigned)(ATTN_ELEMS / 1024), 256>>>(attn_ptr, phi, plo);
        av_gemm<<<dim3(1, 16, BH), 256, SMEM_BYTES>>>(phi, plo, 0);
    } else {
        scores_gemm<<<dim3(16, 16, BH), 256, SMEM_BYTES>>>(mask, attn_ptr, phi, plo, 1);
        av_gemm<<<dim3(1, 16, BH), 256, SMEM_BYTES>>>(phi, plo, 1);
    }
    fc_gemm<<<dim3(8, 64, 1), 256, SMEM_BYTES>>>(out);
}

// round 16
// speedup vs baseline: 1.1495x; 1.1495x over previous
#include <cuda_runtime.h>
#include <cuda_bf16.h>
#include <stdint.h>

#define BATCH 4
#define SEQ   2048
#define EMBD  1024
#define NH    16
#define DKH   64
#define BH    64
#define BSQ   8192
#define QKV_ELEMS  (BATCH * NH * SEQ * DKH)
#define PRED_ELEMS (BSQ * EMBD)
#define ATTN_ELEMS ((size_t)BH * SEQ * SEQ)

__device__ float  g_attn_fb[ATTN_ELEMS];
__device__ int    g_mask_mode;
__device__ float  g_psum[BH * 16 * SEQ];   // per n-tile row partial sums
__device__ float  g_rinv[BH * SEQ];        // 1 / rowsum
__device__ __nv_bfloat16 g_inh[3u * QKV_ELEMS], g_inl[3u * QKV_ELEMS];
__device__ __nv_bfloat16 g_wth[4u * EMBD * EMBD], g_wtl[4u * EMBD * EMBD];
__device__ __nv_bfloat16 g_qh[QKV_ELEMS], g_ql[QKV_ELEMS];
__device__ __nv_bfloat16 g_kh[QKV_ELEMS], g_kl[QKV_ELEMS];
__device__ __nv_bfloat16 g_vh[QKV_ELEMS], g_vl[QKV_ELEMS];
__device__ __nv_bfloat16 g_ph[PRED_ELEMS], g_pl[PRED_ELEMS];

#define OF_AH  1024u
#define OF_AL  (1024u + 16384u)
#define OF_BH  (1024u + 32768u)
#define OF_BL  (1024u + 49152u)
#define SMEM_BYTES (1024 + 4 * 16384)

__device__ __forceinline__ uint32_t smem_u32(const void* p) {
    uint32_t a;
    asm("{ .reg .u64 t; cvta.to.shared.u64 t, %1; cvt.u32.u64 %0, t; }" : "=r"(a) : "l"(p));
    return a;
}
__device__ __forceinline__ void split_bf(float x, __nv_bfloat16& h, __nv_bfloat16& l) {
    h = __float2bfloat16(x);
    l = __float2bfloat16(x - __bfloat162float(h));
}
__device__ __forceinline__ uint32_t pack2(__nv_bfloat16 a, __nv_bfloat16 b) {
    return (uint32_t)__bfloat16_as_ushort(a) | ((uint32_t)__bfloat16_as_ushort(b) << 16);
}
__device__ __forceinline__ void mma16816(float* d, const uint32_t* a, uint32_t b0, uint32_t b1) {
    asm volatile("mma.sync.aligned.m16n8k16.row.col.f32.bf16.bf16.f32 "
                 "{%0,%1,%2,%3}, {%4,%5,%6,%7}, {%8,%9}, {%0,%1,%2,%3};"
                 : "+f"(d[0]), "+f"(d[1]), "+f"(d[2]), "+f"(d[3])
                 : "r"(a[0]), "r"(a[1]), "r"(a[2]), "r"(a[3]), "r"(b0), "r"(b1));
}
__device__ __forceinline__ void ldsm4(uint32_t* r, uint32_t a) {
    asm volatile("ldmatrix.sync.aligned.m8n8.x4.shared.b16 {%0,%1,%2,%3}, [%4];"
                 : "=r"(r[0]), "=r"(r[1]), "=r"(r[2]), "=r"(r[3]) : "r"(a));
}
__device__ __forceinline__ void ldsm4t(uint32_t* r, uint32_t a) {
    asm volatile("ldmatrix.sync.aligned.m8n8.x4.trans.shared.b16 {%0,%1,%2,%3}, [%4];"
                 : "=r"(r[0]), "=r"(r[1]), "=r"(r[2]), "=r"(r[3]) : "r"(a));
}
__device__ __forceinline__ void cp16(uint32_t d, const void* s) {
    asm volatile("cp.async.cg.shared.global [%0], [%1], 16;" :: "r"(d), "l"(s));
}
#define CP_COMMIT() asm volatile("cp.async.commit_group;" ::: "memory")
#define CP_WAIT(n)  asm volatile("cp.async.wait_group %0;" :: "n"(n) : "memory")

__device__ __forceinline__ void cpa(const __nv_bfloat16* __restrict__ s, int ld, uint32_t db,
                                    int st, int tid) {
    for (int i = tid; i < 512; i += 256) {
        const int r = i >> 2, q = i & 3, c = st * 4 + q;
        cp16(db + r * 128 + ((c ^ (r & 7)) << 4), s + (size_t)r * ld + q * 8);
    }
}
__device__ __forceinline__ void cpb(const __nv_bfloat16* __restrict__ s, uint32_t db,
                                    int st, int tid) {
    if (tid < 256) {
        const int r = tid >> 3, q = tid & 7, pr = st * 32 + r;
        cp16(db + pr * 128 + ((q ^ (pr & 7)) << 4), s + (size_t)r * DKH + q * 8);
    }
}

// One K=32 stage; fragment-reuse (R14 form).
template<int NB, bool TRB>
__device__ __forceinline__ void stage_mma(uint32_t sb, int s, int wid, int lane, float* acc) {
    constexpr int NA = NB / 16;
    const int wm = (wid >> 1) * 32, wn = (wid & 1) * (NB / 2);
    const int l15 = lane & 15, lh = lane >> 4;
    #pragma unroll
    for (int kk = 0; kk < 2; ++kk) {
        uint32_t ah[2][4], al[2][4];
        const int ca = s * 4 + kk * 2 + lh;
        #pragma unroll
        for (int im = 0; im < 2; ++im) {
            const int r = wm + im * 16 + l15;
            const uint32_t sw = r * 128 + ((ca ^ (r & 7)) << 4);
            ldsm4(ah[im], sb + OF_AH + sw);
            ldsm4(al[im], sb + OF_AL + sw);
        }
        #pragma unroll
        for (int ap = 0; ap < NA / 2; ++ap) {
            uint32_t bh[4], bl[4];
            if (!TRB) {
                const int r = wn + ap * 16 + l15;
                const uint32_t sw = r * 128 + ((ca ^ (r & 7)) << 4);
                ldsm4(bh, sb + OF_BH + sw);
                ldsm4(bl, sb + OF_BL + sw);
                #pragma unroll
                for (int im = 0; im < 2; ++im) {
                    float* d0 = acc + (im * NA + ap * 2) * 4;
                    float* d1 = acc + (im * NA + ap * 2 + 1) * 4;
                    mma16816(d0, ah[im], bh[0], bh[2]);
                    mma16816(d1, ah[im], bh[1], bh[3]);
                    mma16816(d0, ah[im], bl[0], bl[2]);
                    mma16816(d1, ah[im], bl[1], bl[3]);
                    mma16816(d0, al[im], bh[0], bh[2]);
                    mma16816(d1, al[im], bh[1], bh[3]);
                }
            } else {
                const int r = s * 32 + kk * 16 + l15, c = ((wn + ap * 16) >> 3) + lh;
                const uint32_t sw = r * 128 + ((c ^ (r & 7)) << 4);
                ldsm4t(bh, sb + OF_BH + sw);
                ldsm4t(bl, sb + OF_BL + sw);
                #pragma unroll
                for (int im = 0; im < 2; ++im) {
                    float* d0 = acc + (im * NA + ap * 2) * 4;
                    float* d1 = acc + (im * NA + ap * 2 + 1) * 4;
                    mma16816(d0, ah[im], bh[0], bh[1]);
                    mma16816(d1, ah[im], bh[2], bh[3]);
                    mma16816(d0, ah[im], bl[0], bl[1]);
                    mma16816(d1, ah[im], bl[2], bl[3]);
                    mma16816(d0, al[im], bh[0], bh[1]);
                    mma16816(d1, al[im], bh[2], bh[3]);
                }
            }
        }
    }
}

__global__ void detect_mask_kernel(const unsigned int* __restrict__ m) {
    __shared__ int s01, sf;
    if (threadIdx.x == 0) { s01 = 1; sf = 1; }
    __syncthreads();
    int a01 = 1, af = 1;
    for (int i = threadIdx.x; i < 65536; i += blockDim.x) {
        const unsigned int w = m[i];
        if (w > 1u) a01 = 0;
        if (w != 0u && w != 0x3f800000u) af = 0;
    }
    if (!a01) atomicAnd(&s01, 0);
    if (!af)  atomicAnd(&sf, 0);
    __syncthreads();
    if (threadIdx.x == 0) g_mask_mode = s01 ? 1 : (sf ? 2 : 0);
}

__global__ __launch_bounds__(256) void convert_in_kernel(
    const float* __restrict__ Q, const float* __restrict__ K, const float* __restrict__ V) {
    const int z = blockIdx.z;
    const float* s = (z == 0) ? Q : (z == 1) ? K : V;
    const size_t i = ((size_t)blockIdx.x * 256 + threadIdx.x) * 4;
    const float4 v = *(const float4*)(s + i);
    __nv_bfloat16 h0, h1, h2, h3, l0, l1, l2, l3;
    split_bf(v.x, h0, l0); split_bf(v.y, h1, l1); split_bf(v.z, h2, l2); split_bf(v.w, h3, l3);
    const size_t o = (size_t)z * QKV_ELEMS + i;
    *(uint2*)(g_inh + o) = make_uint2(pack2(h0, h1), pack2(h2, h3));
    *(uint2*)(g_inl + o) = make_uint2(pack2(l0, l1), pack2(l2, l3));
}

__global__ __launch_bounds__(256) void convert_w_kernel(
    const float* __restrict__ WQ, const float* __restrict__ WK,
    const float* __restrict__ WV, const float* __restrict__ Wfc) {
    const int z = blockIdx.z;
    const float* W = (z == 0) ? WQ : (z == 1) ? WK : (z == 2) ? WV : Wfc;
    __shared__ float t[32][33];
    const int tx = threadIdx.x & 31, ty = threadIdx.x >> 5;
    const int x0 = blockIdx.x * 32, y0 = blockIdx.y * 32;
    #pragma unroll
    for (int j = 0; j < 4; ++j)
        t[ty + j * 8][tx] = W[(size_t)(y0 + ty + j * 8) * EMBD + x0 + tx];
    __syncthreads();
    __nv_bfloat16* dh = g_wth + (size_t)z * EMBD * EMBD;
    __nv_bfloat16* dl = g_wtl + (size_t)z * EMBD * EMBD;
    #pragma unroll
    for (int j = 0; j < 4; ++j) {
        __nv_bfloat16 hh, ll;
        split_bf(t[tx][ty + j * 8], hh, ll);
        const size_t o = (size_t)(x0 + ty + j * 8) * EMBD + y0 + tx;
        dh[o] = hh; dl[o] = ll;
    }
}

// QKV projection (R14 form).
__global__ __launch_bounds__(256, 2) void proj_gemm(void) {
    extern __shared__ unsigned char smem[];
    const uint32_t sb = smem_u32(smem);
    const int tid = threadIdx.x, wid = tid >> 5, lane = tid & 31;
    const int z = blockIdx.z, m0 = blockIdx.y * 128, n0 = blockIdx.x * 128;
    const __nv_bfloat16* Ah = g_inh + (size_t)z * QKV_ELEMS + (size_t)m0 * EMBD;
    const __nv_bfloat16* Al = g_inl + (size_t)z * QKV_ELEMS + (size_t)m0 * EMBD;
    const __nv_bfloat16* Bh = g_wth + (size_t)z * EMBD * EMBD + (size_t)n0 * EMBD;
    const __nv_bfloat16* Bl = g_wtl + (size_t)z * EMBD * EMBD + (size_t)n0 * EMBD;
    float acc[64] = {};
    cpa(Ah, EMBD, sb + OF_AH, 0, tid); cpa(Al, EMBD, sb + OF_AL, 0, tid);
    cpa(Bh, EMBD, sb + OF_BH, 0, tid); cpa(Bl, EMBD, sb + OF_BL, 0, tid);
    CP_COMMIT();
    for (int c = 0; c < 32; ++c) {
        if (c < 31) {
            const int k = (c + 1) * 32, s = (c + 1) & 1;
            cpa(Ah + k, EMBD, sb + OF_AH, s, tid); cpa(Al + k, EMBD, sb + OF_AL, s, tid);
            cpa(Bh + k, EMBD, sb + OF_BH, s, tid); cpa(Bl + k, EMBD, sb + OF_BL, s, tid);
            CP_COMMIT(); CP_WAIT(1);
        } else CP_WAIT(0);
        __syncthreads();
        stage_mma<128, false>(sb, c & 1, wid, lane, acc);
        __syncthreads();
    }
    const int gid = lane >> 2, t4 = lane & 3, wm = (wid >> 1) * 32, wn = (wid & 1) * 64;
    __nv_bfloat16* dh = (z == 0) ? g_qh : (z == 1) ? g_kh : g_vh;
    __nv_bfloat16* dl = (z == 0) ? g_ql : (z == 1) ? g_kl : g_vl;
    #pragma unroll
    for (int im = 0; im < 2; ++im)
        #pragma unroll
        for (int ia = 0; ia < 8; ++ia) {
            const float* cc = acc + (im * 8 + ia) * 4;
            const int n = n0 + wn + ia * 8 + t4 * 2, h = n >> 6, d = n & 63;
            #pragma unroll
            for (int hr = 0; hr < 2; ++hr) {
                const int m = m0 + wm + im * 16 + gid + hr * 8;
                const int b = m >> 11, s = m & (SEQ - 1);
                __nv_bfloat16 p0, p1, q0, q1;
                split_bf(cc[hr * 2 + 0], p0, q0);
                split_bf(cc[hr * 2 + 1], p1, q1);
                const size_t o = (((size_t)(b * NH + h)) * SEQ + s) * DKH + d;
                *(uint32_t*)(dh + o) = pack2(p0, p1);
                *(uint32_t*)(dl + o) = pack2(q0, q1);
            }
        }
}

// scores: 128x128 tile, K=64. expout=1: write e=exp(s/8) (masked->0) f32 +
// per-CTA row partial sums to g_psum. expout=0: masked raw scores (attn path).
__global__ __launch_bounds__(256, 2) void scores_gemm(
    const void* __restrict__ mask, float* __restrict__ attn, int expout) {
    extern __shared__ unsigned char smem[];
    const uint32_t sb = smem_u32(smem);
    const int tid = threadIdx.x, wid = tid >> 5, lane = tid & 31;
    const int z = blockIdx.z, b = z >> 4;
    const int m0 = blockIdx.y * 128, n0 = blockIdx.x * 128;
    const size_t zo = (size_t)z * SEQ * DKH;
    const __nv_bfloat16* qh = g_qh + zo + (size_t)m0 * DKH;
    const __nv_bfloat16* ql = g_ql + zo + (size_t)m0 * DKH;
    const __nv_bfloat16* kh = g_kh + zo + (size_t)n0 * DKH;
    const __nv_bfloat16* kl = g_kl + zo + (size_t)n0 * DKH;
    #pragma unroll
    for (int s = 0; s < 2; ++s) {
        cpa(qh + s * 32, DKH, sb + OF_AH, s, tid); cpa(ql + s * 32, DKH, sb + OF_AL, s, tid);
        cpa(kh + s * 32, DKH, sb + OF_BH, s, tid); cpa(kl + s * 32, DKH, sb + OF_BL, s, tid);
    }
    CP_COMMIT(); CP_WAIT(0);
    __syncthreads();
    float acc[64] = {};
    stage_mma<128, false>(sb, 0, wid, lane, acc);
    stage_mma<128, false>(sb, 1, wid, lane, acc);
    __syncthreads();
    {
        const int mode = g_mask_mode;
        for (int i = tid; i < 128 * 32; i += 256) {
            const int r = i >> 5, c0 = (i & 31) * 4;
            const size_t g = ((size_t)b * SEQ + m0 + r) * SEQ + n0 + c0;
            uint32_t f4;
            if (mode == 1) {
                const int4 w = *(const int4*)((const int*)mask + g);
                f4 = (w.x?1u:0u) | ((w.y?1u:0u)<<8) | ((w.z?1u:0u)<<16) | ((w.w?1u:0u)<<24);
            } else if (mode == 2) {
                const float4 w = *(const float4*)((const float*)mask + g);
                f4 = (w.x!=0.f?1u:0u) | ((w.y!=0.f?1u:0u)<<8) | ((w.z!=0.f?1u:0u)<<16) | ((w.w!=0.f?1u:0u)<<24);
            } else {
                f4 = *(const uint32_t*)((const unsigned char*)mask + g);
            }
            *(uint32_t*)(smem + OF_AH + r * 132 + c0) = f4;
        }
    }
    __syncthreads();
    const int gid = lane >> 2, t4 = lane & 3, wm = (wid >> 1) * 32, wn = (wid & 1) * 64;
    float rs[4] = {};
    #pragma unroll
    for (int im = 0; im < 2; ++im)
        #pragma unroll
        for (int ia = 0; ia < 8; ++ia) {
            const float* cc = acc + (im * 8 + ia) * 4;
            const int ln = wn + ia * 8 + t4 * 2;
            #pragma unroll
            for (int hr = 0; hr < 2; ++hr) {
                const int rl = wm + im * 16 + gid + hr * 8;
                const unsigned char* fr = smem + OF_AH + rl * 132 + ln;
                const size_t go = ((size_t)z * SEQ + m0 + rl) * SEQ + n0 + ln;
                float2 o;
                if (expout) {
                    o.x = fr[0] ? 0.f : __expf(cc[hr * 2 + 0] * 0.125f);
                    o.y = fr[1] ? 0.f : __expf(cc[hr * 2 + 1] * 0.125f);
                    rs[im * 2 + hr] += o.x + o.y;
                } else {
                    o.x = fr[0] ? -1e9f : cc[hr * 2 + 0] * 0.125f;
                    o.y = fr[1] ? -1e9f : cc[hr * 2 + 1] * 0.125f;
                }
                *(float2*)(attn + go) = o;
            }
        }
    if (expout) {
        float* srow = (float*)smem;        // [128][2] floats, bytes 0..1023
        #pragma unroll
        for (int j = 0; j < 4; ++j) {
            rs[j] += __shfl_xor_sync(0xffffffffu, rs[j], 1);
            rs[j] += __shfl_xor_sync(0xffffffffu, rs[j], 2);
        }
        if (t4 == 0)
            #pragma unroll
            for (int j = 0; j < 4; ++j) {
                const int rl = wm + (j >> 1) * 16 + gid + (j & 1) * 8;
                srow[rl * 2 + (wid & 1)] = rs[j];
            }
        __syncthreads();
        if (tid < 128)
            g_psum[((size_t)z * 16 + blockIdx.x) * SEQ + m0 + tid] =
                srow[tid * 2] + srow[tid * 2 + 1];
    }
}

// reduce 16 n-tile partials per row -> 1/rowsum. Deterministic fixed order.
__global__ __launch_bounds__(256) void rinv_kernel(void) {
    const int idx = blockIdx.x * 256 + threadIdx.x;   // z*SEQ + m
    const int z = idx >> 11, m = idx & (SEQ - 1);
    float s = 0.f;
    #pragma unroll
    for (int j = 0; j < 16; ++j)
        s += g_psum[((size_t)z * 16 + j) * SEQ + m];
    g_rinv[idx] = 1.0f / s;
}

__global__ __launch_bounds__(256) void softmax_kernel(float* __restrict__ attn) {
    float* p = attn + (size_t)blockIdx.x * SEQ;
    const int t = threadIdx.x;
    float v[8], m = -3.4e38f;
    #pragma unroll
    for (int j = 0; j < 8; ++j) { v[j] = p[t + j * 256]; m = fmaxf(m, v[j]); }
    __shared__ float red[8]; __shared__ float bmax, bsum;
    #pragma unroll
    for (int o = 16; o > 0; o >>= 1) m = fmaxf(m, __shfl_xor_sync(0xffffffffu, m, o));
    if ((t & 31) == 0) red[t >> 5] = m;
    __syncthreads();
    if (t == 0) {
        float mm = red[0];
        #pragma unroll
        for (int i = 1; i < 8; ++i) mm = fmaxf(mm, red[i]);
        bmax = mm;
    }
    __syncthreads();
    m = bmax;
    float s = 0.f;
    #pragma unroll
    for (int j = 0; j < 8; ++j) { v[j] = __expf(v[j] - m); s += v[j]; }
    __syncthreads();
    #pragma unroll
    for (int o = 16; o > 0; o >>= 1) s += __shfl_xor_sync(0xffffffffu, s, o);
    if ((t & 31) == 0) red[t >> 5] = s;
    __syncthreads();
    if (t == 0) {
        float ss = red[0];
        #pragma unroll
        for (int i = 1; i < 8; ++i) ss += red[i];
        bsum = ss;
    }
    __syncthreads();
    const float inv = 1.0f / bsum;
    #pragma unroll
    for (int j = 0; j < 8; ++j) p[t + j * 256] = v[j] * inv;
}

// av (R14 form): A f32 register prefetch (* rinv if scaled) -> split STS; B cp.async.
__global__ __launch_bounds__(256, 2) void av_gemm(const float* __restrict__ attn, int scaled) {
    extern __shared__ unsigned char smem[];
    const uint32_t sb = smem_u32(smem);
    const int tid = threadIdx.x, wid = tid >> 5, lane = tid & 31;
    const int z = blockIdx.z, b = z >> 4, h = z & 15, m0 = blockIdx.y * 128;
    const size_t zo = (size_t)z * SEQ * DKH;
    const float* Ab = attn + ((size_t)z * SEQ + m0) * SEQ;
    float* st = (float*)smem;              // 128 floats
    if (tid < 128) st[tid] = scaled ? g_rinv[(size_t)z * SEQ + m0 + tid] : 1.0f;
    float4 pa[4];
    #pragma unroll
    for (int j = 0; j < 4; ++j) {
        const int i = tid + j * 256;
        pa[j] = *(const float4*)(Ab + (size_t)(i >> 3) * SEQ + (i & 7) * 4);
    }
    cpb(g_vh + zo, sb + OF_BH, 0, tid);
    cpb(g_vl + zo, sb + OF_BL, 0, tid);
    CP_COMMIT();
    __syncthreads();
    float acc[32] = {};
    for (int c = 0; c < 64; ++c) {
        const int s = c & 1;
        #pragma unroll
        for (int j = 0; j < 4; ++j) {
            const int i = tid + j * 256, r = i >> 3, q = i & 7;
            float4 v = pa[j];
            const float w = st[r];
            v.x *= w; v.y *= w; v.z *= w; v.w *= w;
            __nv_bfloat16 h0, h1, h2, h3, l0, l1, l2, l3;
            split_bf(v.x, h0, l0); split_bf(v.y, h1, l1);
            split_bf(v.z, h2, l2); split_bf(v.w, h3, l3);
            const int cch = s * 4 + (q >> 1);
            const uint32_t ad = r * 128 + ((cch ^ (r & 7)) << 4) + (q & 1) * 8;
            *(uint2*)(smem + OF_AH + ad) = make_uint2(pack2(h0, h1), pack2(h2, h3));
            *(uint2*)(smem + OF_AL + ad) = make_uint2(pack2(l0, l1), pack2(l2, l3));
        }
        if (c < 63) {
            const int k = (c + 1) * 32, sn = (c + 1) & 1;
            #pragma unroll
            for (int j = 0; j < 4; ++j) {
                const int i = tid + j * 256;
                pa[j] = *(const float4*)(Ab + (size_t)(i >> 3) * SEQ + k + (i & 7) * 4);
            }
            cpb(g_vh + zo + (size_t)k * DKH, sb + OF_BH, sn, tid);
            cpb(g_vl + zo + (size_t)k * DKH, sb + OF_BL, sn, tid);
            CP_COMMIT(); CP_WAIT(1);
        } else CP_WAIT(0);
        __syncthreads();
        stage_mma<64, true>(sb, s, wid, lane, acc);
        __syncthreads();
    }
    const int gid = lane >> 2, t4 = lane & 3, wm = (wid >> 1) * 32, wn = (wid & 1) * 32;
    #pragma unroll
    for (int im = 0; im < 2; ++im)
        #pragma unroll
        for (int ia = 0; ia < 4; ++ia) {
            const float* cc = acc + (im * 4 + ia) * 4;
            const int d = wn + ia * 8 + t4 * 2;
            #pragma unroll
            for (int hr = 0; hr < 2; ++hr) {
                const int m = m0 + wm + im * 16 + gid + hr * 8;
                __nv_bfloat16 p0, p1, q0, q1;
                split_bf(cc[hr * 2 + 0], p0, q0);
                split_bf(cc[hr * 2 + 1], p1, q1);
                const size_t o = ((size_t)(b * SEQ + m)) * EMBD + h * 64 + d;
                *(uint32_t*)(g_ph + o) = pack2(p0, p1);
                *(uint32_t*)(g_pl + o) = pack2(q0, q1);
            }
        }
}

// fc (R14 form).
__global__ __launch_bounds__(256, 2) void fc_gemm(float* __restrict__ out) {
    extern __shared__ unsigned char smem[];
    const uint32_t sb = smem_u32(smem);
    const int tid = threadIdx.x, wid = tid >> 5, lane = tid & 31;
    const int m0 = blockIdx.y * 128, n0 = blockIdx.x * 128;
    const __nv_bfloat16* Ah = g_ph + (size_t)m0 * EMBD;
    const __nv_bfloat16* Al = g_pl + (size_t)m0 * EMBD;
    const __nv_bfloat16* Bh = g_wth + (size_t)3 * EMBD * EMBD + (size_t)n0 * EMBD;
    const __nv_bfloat16* Bl = g_wtl + (size_t)3 * EMBD * EMBD + (size_t)n0 * EMBD;
    float acc[64] = {};
    cpa(Ah, EMBD, sb + OF_AH, 0, tid); cpa(Al, EMBD, sb + OF_AL, 0, tid);
    cpa(Bh, EMBD, sb + OF_BH, 0, tid); cpa(Bl, EMBD, sb + OF_BL, 0, tid);
    CP_COMMIT();
    for (int c = 0; c < 32; ++c) {
        if (c < 31) {
            const int k = (c + 1) * 32, s = (c + 1) & 1;
            cpa(Ah + k, EMBD, sb + OF_AH, s, tid); cpa(Al + k, EMBD, sb + OF_AL, s, tid);
            cpa(Bh + k, EMBD, sb + OF_BH, s, tid); cpa(Bl + k, EMBD, sb + OF_BL, s, tid);
            CP_COMMIT(); CP_WAIT(1);
        } else CP_WAIT(0);
        __syncthreads();
        stage_mma<128, false>(sb, c & 1, wid, lane, acc);
        __syncthreads();
    }
    const int gid = lane >> 2, t4 = lane & 3, wm = (wid >> 1) * 32, wn = (wid & 1) * 64;
    #pragma unroll
    for (int im = 0; im < 2; ++im)
        #pragma unroll
        for (int ia = 0; ia < 8; ++ia) {
            const float* cc = acc + (im * 8 + ia) * 4;
            const int n = n0 + wn + ia * 8 + t4 * 2;
            #pragma unroll
            for (int hr = 0; hr < 2; ++hr) {
                const int m = m0 + wm + im * 16 + gid + hr * 8;
                *(float2*)(out + (size_t)m * EMBD + n) =
                    make_float2(cc[hr * 2 + 0], cc[hr * 2 + 1]);
            }
        }
}

extern "C" void kernel_launch(void* const* d_in, const int* in_sizes, int n_in,
                              void* d_out, int out_size) {
    const float* Q = (const float*)d_in[0];
    const float* K = (const float*)d_in[1];
    const float* V = (const float*)d_in[2];
    const void* mask = d_in[3];
    const float* WQ = (const float*)d_in[4];
    const float* WK = (const float*)d_in[5];
    const float* WV = (const float*)d_in[6];
    const float* Wfc = (const float*)d_in[7];
    float* out = (float*)d_out;

    const int attn_out = (out_size >= (int)(PRED_ELEMS + ATTN_ELEMS));
    float* attn_ptr;
    if (attn_out) {
        attn_ptr = out + PRED_ELEMS;
    } else {
        void* p = nullptr;
        cudaGetSymbolAddress(&p, g_attn_fb);
        attn_ptr = (float*)p;
    }

    cudaFuncSetAttribute(proj_gemm,   cudaFuncAttributeMaxDynamicSharedMemorySize, SMEM_BYTES);
    cudaFuncSetAttribute(scores_gemm, cudaFuncAttributeMaxDynamicSharedMemorySize, SMEM_BYTES);
    cudaFuncSetAttribute(av_gemm,     cudaFuncAttributeMaxDynamicSharedMemorySize, SMEM_BYTES);
    cudaFuncSetAttribute(fc_gemm,     cudaFuncAttributeMaxDynamicSharedMemorySize, SMEM_BYTES);

    detect_mask_kernel<<<1, 1024>>>((const unsigned int*)mask);
    convert_in_kernel<<<dim3(QKV_ELEMS / 1024, 1, 3), 256>>>(Q, K, V);
    convert_w_kernel<<<dim3(32, 32, 4), 256>>>(WQ, WK, WV, Wfc);
    proj_gemm<<<dim3(8, 64, 3), 256, SMEM_BYTES>>>();
    if (attn_out) {
        scores_gemm<<<dim3(16, 16, BH), 256, SMEM_BYTES>>>(mask, attn_ptr, 0);
        softmax_kernel<<<BH * SEQ, 256>>>(attn_ptr);
        av_gemm<<<dim3(1, 16, BH), 256, SMEM_BYTES>>>(attn_ptr, 0);
    } else {
        scores_gemm<<<dim3(16, 16, BH), 256, SMEM_BYTES>>>(mask, attn_ptr, 1);
        rinv_kernel<<<BH * SEQ / 256, 256>>>();
        av_gemm<<<dim3(1, 16, BH), 256, SMEM_BYTES>>>(attn_ptr, 1);
    }
    fc_gemm<<<dim3(8, 64, 1), 256, SMEM_BYTES>>>(out);
}

// round 17
// speedup vs baseline: 1.1661x; 1.0145x over previous
#include <cuda_runtime.h>
#include <cuda_bf16.h>
#include <stdint.h>

#define BATCH 4
#define SEQ   2048
#define EMBD  1024
#define NH    16
#define DKH   64
#define BH    64
#define BSQ   8192
#define QKV_ELEMS  (BATCH * NH * SEQ * DKH)
#define PRED_ELEMS (BSQ * EMBD)
#define ATTN_ELEMS ((size_t)BH * SEQ * SEQ)

__device__ float  g_attn_fb[ATTN_ELEMS];
__device__ int    g_mask_mode;
__device__ __nv_bfloat16 g_inh[3u * QKV_ELEMS], g_inl[3u * QKV_ELEMS];
__device__ __nv_bfloat16 g_wth[4u * EMBD * EMBD], g_wtl[4u * EMBD * EMBD];
__device__ __nv_bfloat16 g_qh[QKV_ELEMS], g_ql[QKV_ELEMS];
__device__ __nv_bfloat16 g_kh[QKV_ELEMS], g_kl[QKV_ELEMS];
__device__ __nv_bfloat16 g_vh[QKV_ELEMS], g_vl[QKV_ELEMS];
__device__ __nv_bfloat16 g_ph[PRED_ELEMS], g_pl[PRED_ELEMS];

#define OF_AH  1024u
#define OF_AL  (1024u + 16384u)
#define OF_BH  (1024u + 32768u)
#define OF_BL  (1024u + 49152u)
#define SMEM_BYTES (1024 + 4 * 16384)

// fused attn smem layout
#define AQ_H 0u
#define AQ_L 16384u
#define AK_H 32768u
#define AK_L 40960u
#define AV_B 49152u              // 2 slots x (VH 8K | VL 8K)
#define AP_H 81920u
#define AP_L 98304u
#define ARED 114688u
#define ATT_SMEM (114688u + 1024u)

__device__ __forceinline__ uint32_t smem_u32(const void* p) {
    uint32_t a;
    asm("{ .reg .u64 t; cvta.to.shared.u64 t, %1; cvt.u32.u64 %0, t; }" : "=r"(a) : "l"(p));
    return a;
}
__device__ __forceinline__ void split_bf(float x, __nv_bfloat16& h, __nv_bfloat16& l) {
    h = __float2bfloat16(x);
    l = __float2bfloat16(x - __bfloat162float(h));
}
__device__ __forceinline__ uint32_t pack2(__nv_bfloat16 a, __nv_bfloat16 b) {
    return (uint32_t)__bfloat16_as_ushort(a) | ((uint32_t)__bfloat16_as_ushort(b) << 16);
}
__device__ __forceinline__ void mma16816(float* d, const uint32_t* a, uint32_t b0, uint32_t b1) {
    asm volatile("mma.sync.aligned.m16n8k16.row.col.f32.bf16.bf16.f32 "
                 "{%0,%1,%2,%3}, {%4,%5,%6,%7}, {%8,%9}, {%0,%1,%2,%3};"
                 : "+f"(d[0]), "+f"(d[1]), "+f"(d[2]), "+f"(d[3])
                 : "r"(a[0]), "r"(a[1]), "r"(a[2]), "r"(a[3]), "r"(b0), "r"(b1));
}
__device__ __forceinline__ void ldsm4(uint32_t* r, uint32_t a) {
    asm volatile("ldmatrix.sync.aligned.m8n8.x4.shared.b16 {%0,%1,%2,%3}, [%4];"
                 : "=r"(r[0]), "=r"(r[1]), "=r"(r[2]), "=r"(r[3]) : "r"(a));
}
__device__ __forceinline__ void ldsm4t(uint32_t* r, uint32_t a) {
    asm volatile("ldmatrix.sync.aligned.m8n8.x4.trans.shared.b16 {%0,%1,%2,%3}, [%4];"
                 : "=r"(r[0]), "=r"(r[1]), "=r"(r[2]), "=r"(r[3]) : "r"(a));
}
__device__ __forceinline__ void cp16(uint32_t d, const void* s) {
    asm volatile("cp.async.cg.shared.global [%0], [%1], 16;" :: "r"(d), "l"(s));
}
#define CP_COMMIT() asm volatile("cp.async.commit_group;" ::: "memory")
#define CP_WAIT(n)  asm volatile("cp.async.wait_group %0;" :: "n"(n) : "memory")

__device__ __forceinline__ void cpa(const __nv_bfloat16* __restrict__ s, int ld, uint32_t db,
                                    int st, int tid) {
    for (int i = tid; i < 512; i += 256) {
        const int r = i >> 2, q = i & 3, c = st * 4 + q;
        cp16(db + r * 128 + ((c ^ (r & 7)) << 4), s + (size_t)r * ld + q * 8);
    }
}
__device__ __forceinline__ void cpb(const __nv_bfloat16* __restrict__ s, uint32_t db,
                                    int st, int tid) {
    if (tid < 256) {
        const int r = tid >> 3, q = tid & 7, pr = st * 32 + r;
        cp16(db + pr * 128 + ((q ^ (pr & 7)) << 4), s + (size_t)r * DKH + q * 8);
    }
}
// [rows x 64] bf16 -> full swizzled 128B-row tile, 512 threads.
__device__ __forceinline__ void cpt(const __nv_bfloat16* __restrict__ s, uint32_t db,
                                    int rows, int tid) {
    for (int i = tid; i < rows * 8; i += 512) {
        const int r = i >> 3, q = i & 7;
        cp16(db + r * 128 + ((q ^ (r & 7)) << 4), s + (size_t)r * DKH + q * 8);
    }
}

// One K=32 stage (256-thread GEMMs); fragment-reuse.
template<int NB, bool TRB>
__device__ __forceinline__ void stage_mma(uint32_t sb, int s, int wid, int lane, float* acc) {
    constexpr int NA = NB / 16;
    const int wm = (wid >> 1) * 32, wn = (wid & 1) * (NB / 2);
    const int l15 = lane & 15, lh = lane >> 4;
    #pragma unroll
    for (int kk = 0; kk < 2; ++kk) {
        uint32_t ah[2][4], al[2][4];
        const int ca = s * 4 + kk * 2 + lh;
        #pragma unroll
        for (int im = 0; im < 2; ++im) {
            const int r = wm + im * 16 + l15;
            const uint32_t sw = r * 128 + ((ca ^ (r & 7)) << 4);
            ldsm4(ah[im], sb + OF_AH + sw);
            ldsm4(al[im], sb + OF_AL + sw);
        }
        #pragma unroll
        for (int ap = 0; ap < NA / 2; ++ap) {
            uint32_t bh[4], bl[4];
            if (!TRB) {
                const int r = wn + ap * 16 + l15;
                const uint32_t sw = r * 128 + ((ca ^ (r & 7)) << 4);
                ldsm4(bh, sb + OF_BH + sw);
                ldsm4(bl, sb + OF_BL + sw);
                #pragma unroll
                for (int im = 0; im < 2; ++im) {
                    float* d0 = acc + (im * NA + ap * 2) * 4;
                    float* d1 = acc + (im * NA + ap * 2 + 1) * 4;
                    mma16816(d0, ah[im], bh[0], bh[2]);
                    mma16816(d1, ah[im], bh[1], bh[3]);
                    mma16816(d0, ah[im], bl[0], bl[2]);
                    mma16816(d1, ah[im], bl[1], bl[3]);
                    mma16816(d0, al[im], bh[0], bh[2]);
                    mma16816(d1, al[im], bh[1], bh[3]);
                }
            } else {
                const int r = s * 32 + kk * 16 + l15, c = ((wn + ap * 16) >> 3) + lh;
                const uint32_t sw = r * 128 + ((c ^ (r & 7)) << 4);
                ldsm4t(bh, sb + OF_BH + sw);
                ldsm4t(bl, sb + OF_BL + sw);
                #pragma unroll
                for (int im = 0; im < 2; ++im) {
                    float* d0 = acc + (im * NA + ap * 2) * 4;
                    float* d1 = acc + (im * NA + ap * 2 + 1) * 4;
                    mma16816(d0, ah[im], bh[0], bh[1]);
                    mma16816(d1, ah[im], bh[2], bh[3]);
                    mma16816(d0, ah[im], bl[0], bl[1]);
                    mma16816(d1, ah[im], bl[2], bl[3]);
                    mma16816(d0, al[im], bh[0], bh[1]);
                    mma16816(d1, al[im], bh[2], bh[3]);
                }
            }
        }
    }
}

__global__ void detect_mask_kernel(const unsigned int* __restrict__ m) {
    __shared__ int s01, sf;
    if (threadIdx.x == 0) { s01 = 1; sf = 1; }
    __syncthreads();
    int a01 = 1, af = 1;
    for (int i = threadIdx.x; i < 65536; i += blockDim.x) {
        const unsigned int w = m[i];
        if (w > 1u) a01 = 0;
        if (w != 0u && w != 0x3f800000u) af = 0;
    }
    if (!a01) atomicAnd(&s01, 0);
    if (!af)  atomicAnd(&sf, 0);
    __syncthreads();
    if (threadIdx.x == 0) g_mask_mode = s01 ? 1 : (sf ? 2 : 0);
}

__global__ __launch_bounds__(256) void convert_in_kernel(
    const float* __restrict__ Q, const float* __restrict__ K, const float* __restrict__ V) {
    const int z = blockIdx.z;
    const float* s = (z == 0) ? Q : (z == 1) ? K : V;
    const size_t i = ((size_t)blockIdx.x * 256 + threadIdx.x) * 4;
    const float4 v = *(const float4*)(s + i);
    __nv_bfloat16 h0, h1, h2, h3, l0, l1, l2, l3;
    split_bf(v.x, h0, l0); split_bf(v.y, h1, l1); split_bf(v.z, h2, l2); split_bf(v.w, h3, l3);
    const size_t o = (size_t)z * QKV_ELEMS + i;
    *(uint2*)(g_inh + o) = make_uint2(pack2(h0, h1), pack2(h2, h3));
    *(uint2*)(g_inl + o) = make_uint2(pack2(l0, l1), pack2(l2, l3));
}

__global__ __launch_bounds__(256) void convert_w_kernel(
    const float* __restrict__ WQ, const float* __restrict__ WK,
    const float* __restrict__ WV, const float* __restrict__ Wfc) {
    const int z = blockIdx.z;
    const float* W = (z == 0) ? WQ : (z == 1) ? WK : (z == 2) ? WV : Wfc;
    __shared__ float t[32][33];
    const int tx = threadIdx.x & 31, ty = threadIdx.x >> 5;
    const int x0 = blockIdx.x * 32, y0 = blockIdx.y * 32;
    #pragma unroll
    for (int j = 0; j < 4; ++j)
        t[ty + j * 8][tx] = W[(size_t)(y0 + ty + j * 8) * EMBD + x0 + tx];
    __syncthreads();
    __nv_bfloat16* dh = g_wth + (size_t)z * EMBD * EMBD;
    __nv_bfloat16* dl = g_wtl + (size_t)z * EMBD * EMBD;
    #pragma unroll
    for (int j = 0; j < 4; ++j) {
        __nv_bfloat16 hh, ll;
        split_bf(t[tx][ty + j * 8], hh, ll);
        const size_t o = (size_t)(x0 + ty + j * 8) * EMBD + y0 + tx;
        dh[o] = hh; dl[o] = ll;
    }
}

__global__ __launch_bounds__(256, 2) void proj_gemm(void) {
    extern __shared__ unsigned char smem[];
    const uint32_t sb = smem_u32(smem);
    const int tid = threadIdx.x, wid = tid >> 5, lane = tid & 31;
    const int z = blockIdx.z, m0 = blockIdx.y * 128, n0 = blockIdx.x * 128;
    const __nv_bfloat16* Ah = g_inh + (size_t)z * QKV_ELEMS + (size_t)m0 * EMBD;
    const __nv_bfloat16* Al = g_inl + (size_t)z * QKV_ELEMS + (size_t)m0 * EMBD;
    const __nv_bfloat16* Bh = g_wth + (size_t)z * EMBD * EMBD + (size_t)n0 * EMBD;
    const __nv_bfloat16* Bl = g_wtl + (size_t)z * EMBD * EMBD + (size_t)n0 * EMBD;
    float acc[64] = {};
    cpa(Ah, EMBD, sb + OF_AH, 0, tid); cpa(Al, EMBD, sb + OF_AL, 0, tid);
    cpa(Bh, EMBD, sb + OF_BH, 0, tid); cpa(Bl, EMBD, sb + OF_BL, 0, tid);
    CP_COMMIT();
    for (int c = 0; c < 32; ++c) {
        if (c < 31) {
            const int k = (c + 1) * 32, s = (c + 1) & 1;
            cpa(Ah + k, EMBD, sb + OF_AH, s, tid); cpa(Al + k, EMBD, sb + OF_AL, s, tid);
            cpa(Bh + k, EMBD, sb + OF_BH, s, tid); cpa(Bl + k, EMBD, sb + OF_BL, s, tid);
            CP_COMMIT(); CP_WAIT(1);
        } else CP_WAIT(0);
        __syncthreads();
        stage_mma<128, false>(sb, c & 1, wid, lane, acc);
        __syncthreads();
    }
    const int gid = lane >> 2, t4 = lane & 3, wm = (wid >> 1) * 32, wn = (wid & 1) * 64;
    __nv_bfloat16* dh = (z == 0) ? g_qh : (z == 1) ? g_kh : g_vh;
    __nv_bfloat16* dl = (z == 0) ? g_ql : (z == 1) ? g_kl : g_vl;
    #pragma unroll
    for (int im = 0; im < 2; ++im)
        #pragma unroll
        for (int ia = 0; ia < 8; ++ia) {
            const float* cc = acc + (im * 8 + ia) * 4;
            const int n = n0 + wn + ia * 8 + t4 * 2, h = n >> 6, d = n & 63;
            #pragma unroll
            for (int hr = 0; hr < 2; ++hr) {
                const int m = m0 + wm + im * 16 + gid + hr * 8;
                const int b = m >> 11, s = m & (SEQ - 1);
                __nv_bfloat16 p0, p1, q0, q1;
                split_bf(cc[hr * 2 + 0], p0, q0);
                split_bf(cc[hr * 2 + 1], p1, q1);
                const size_t o = (((size_t)(b * NH + h)) * SEQ + s) * DKH + d;
                *(uint32_t*)(dh + o) = pack2(p0, p1);
                *(uint32_t*)(dl + o) = pack2(q0, q1);
            }
        }
}

// ---------------------------------------------------------------------------
// Fused attention (no attn output): per CTA one 128-row q-tile of one head.
// 512 threads, 16 warps as 8(m) x 2(n); loop 32 key tiles of 64.
// S = QK^T (bf16x3), p = exp(s/8) masked->0 (row sums in regs), O += P V.
// ---------------------------------------------------------------------------
__global__ __launch_bounds__(512, 1) void attn_fused(const void* __restrict__ mask) {
    extern __shared__ unsigned char smem[];
    const uint32_t sb = smem_u32(smem);
    const int tid = threadIdx.x, wid = tid >> 5, lane = tid & 31;
    const int l15 = lane & 15, lh = lane >> 4, gid = lane >> 2, t4 = lane & 3;
    const int z = blockIdx.y, b = z >> 4, h = z & 15, m0 = blockIdx.x * 128;
    const size_t zo = (size_t)z * SEQ * DKH;
    const int wm = (wid >> 1) * 16, wn = (wid & 1) * 32;
    const int mode = g_mask_mode;

    cpt(g_qh + zo + (size_t)m0 * DKH, sb + AQ_H, 128, tid);
    cpt(g_ql + zo + (size_t)m0 * DKH, sb + AQ_L, 128, tid);
    cpt(g_kh + zo, sb + AK_H, 64, tid);
    cpt(g_kl + zo, sb + AK_L, 64, tid);
    CP_COMMIT();                                   // group: Q + K0
    cpt(g_vh + zo, sb + AV_B, 64, tid);
    cpt(g_vl + zo, sb + AV_B + 8192u, 64, tid);
    CP_COMMIT();                                   // group: V0

    float oacc[16] = {}, rs[2] = {};
    for (int kt = 0; kt < 32; ++kt) {
        CP_WAIT(1);
        __syncthreads();                           // Q(+K kt) ready, prior iter done
        float sacc[16] = {};
        #pragma unroll
        for (int s = 0; s < 2; ++s)
            #pragma unroll
            for (int kk = 0; kk < 2; ++kk) {
                const int ca = s * 4 + kk * 2 + lh;
                uint32_t ah[4], al[4];
                { const int r = wm + l15;
                  const uint32_t sw = r * 128 + ((ca ^ (r & 7)) << 4);
                  ldsm4(ah, sb + AQ_H + sw); ldsm4(al, sb + AQ_L + sw); }
                #pragma unroll
                for (int ap = 0; ap < 2; ++ap) {
                    uint32_t bh[4], bl[4];
                    const int r = wn + ap * 16 + l15;
                    const uint32_t sw = r * 128 + ((ca ^ (r & 7)) << 4);
                    ldsm4(bh, sb + AK_H + sw); ldsm4(bl, sb + AK_L + sw);
                    float* d0 = sacc + (ap * 2) * 4;
                    float* d1 = sacc + (ap * 2 + 1) * 4;
                    mma16816(d0, ah, bh[0], bh[2]); mma16816(d1, ah, bh[1], bh[3]);
                    mma16816(d0, ah, bl[0], bl[2]); mma16816(d1, ah, bl[1], bl[3]);
                    mma16816(d0, al, bh[0], bh[2]); mma16816(d1, al, bh[1], bh[3]);
                }
            }
        __syncthreads();                           // all warps done reading K
        if (kt < 31) {                             // prefetch K(kt+1)
            const size_t ko = zo + (size_t)(kt + 1) * 64 * DKH;
            cpt(g_kh + ko, sb + AK_H, 64, tid);
            cpt(g_kl + ko, sb + AK_L, 64, tid);
        }
        CP_COMMIT();
        // mask + exp + P write + row partial sums
        const int n0k = kt * 64;
        #pragma unroll
        for (int ia = 0; ia < 4; ++ia) {
            float* cc = sacc + ia * 4;
            const int ln = wn + ia * 8 + t4 * 2;
            #pragma unroll
            for (int hr = 0; hr < 2; ++hr) {
                const int rl = wm + gid + hr * 8;
                const size_t mg = ((size_t)b * SEQ + m0 + rl) * SEQ + n0k + ln;
                bool k0, k1;
                if (mode == 1) {
                    const int2 w = *(const int2*)((const int*)mask + mg);
                    k0 = w.x != 0; k1 = w.y != 0;
                } else if (mode == 2) {
                    const float2 w = *(const float2*)((const float*)mask + mg);
                    k0 = w.x != 0.f; k1 = w.y != 0.f;
                } else {
                    const unsigned char* w = (const unsigned char*)mask + mg;
                    k0 = w[0] != 0; k1 = w[1] != 0;
                }
                const float p0 = k0 ? 0.f : __expf(cc[hr * 2 + 0] * 0.125f);
                const float p1 = k1 ? 0.f : __expf(cc[hr * 2 + 1] * 0.125f);
                rs[hr] += p0 + p1;
                __nv_bfloat16 h0, l0, h1, l1;
                split_bf(p0, h0, l0); split_bf(p1, h1, l1);
                const uint32_t po = rl * 128 + (((ln >> 3) ^ (rl & 7)) << 4) + (ln & 7) * 2;
                *(uint32_t*)(smem + AP_H + po) = pack2(h0, h1);
                *(uint32_t*)(smem + AP_L + po) = pack2(l0, l1);
            }
        }
        CP_WAIT(1);                                 // V(kt) done (K(kt+1) may pend)
        __syncthreads();                            // P visible
        // O += P V
        const uint32_t vb = AV_B + (uint32_t)(kt & 1) * 16384u;
        #pragma unroll
        for (int s = 0; s < 2; ++s)
            #pragma unroll
            for (int kk = 0; kk < 2; ++kk) {
                const int ca = s * 4 + kk * 2 + lh;
                uint32_t ah[4], al[4];
                { const int r = wm + l15;
                  const uint32_t sw = r * 128 + ((ca ^ (r & 7)) << 4);
                  ldsm4(ah, sb + AP_H + sw); ldsm4(al, sb + AP_L + sw); }
                #pragma unroll
                for (int ap = 0; ap < 2; ++ap) {
                    uint32_t bh[4], bl[4];
                    const int r = s * 32 + kk * 16 + l15;
                    const int c = ((wn + ap * 16) >> 3) + lh;
                    const uint32_t sw = r * 128 + ((c ^ (r & 7)) << 4);
                    ldsm4t(bh, sb + vb + sw); ldsm4t(bl, sb + vb + 8192u + sw);
                    float* d0 = oacc + (ap * 2) * 4;
                    float* d1 = oacc + (ap * 2 + 1) * 4;
                    mma16816(d0, ah, bh[0], bh[1]); mma16816(d1, ah, bh[2], bh[3]);
                    mma16816(d0, ah, bl[0], bl[1]); mma16816(d1, ah, bl[2], bl[3]);
                    mma16816(d0, al, bh[0], bh[1]); mma16816(d1, al, bh[2], bh[3]);
                }
            }
        if (kt < 31) {                              // prefetch V(kt+1), other slot
            const size_t vo = zo + (size_t)(kt + 1) * 64 * DKH;
            const uint32_t vs = AV_B + (uint32_t)((kt + 1) & 1) * 16384u;
            cpt(g_vh + vo, sb + vs, 64, tid);
            cpt(g_vl + vo, sb + vs + 8192u, 64, tid);
        }
        CP_COMMIT();
    }
    // row-sum reduction (deterministic): quad shfl + cross-n-warp via smem.
    #pragma unroll
    for (int hr = 0; hr < 2; ++hr) {
        float v = rs[hr];
        v += __shfl_xor_sync(0xffffffffu, v, 1);
        v += __shfl_xor_sync(0xffffffffu, v, 2);
        rs[hr] = v;
    }
    float* sred = (float*)(smem + ARED);
    if (t4 == 0) {
        sred[(wm + gid) * 2 + (wid & 1)] = rs[0];
        sred[(wm + gid + 8) * 2 + (wid & 1)] = rs[1];
    }
    __syncthreads();
    float inv[2];
    #pragma unroll
    for (int hr = 0; hr < 2; ++hr) {
        const int rl = wm + gid + hr * 8;
        inv[hr] = 1.0f / (sred[rl * 2] + sred[rl * 2 + 1]);
    }
    #pragma unroll
    for (int ia = 0; ia < 4; ++ia) {
        const float* cc = oacc + ia * 4;
        const int d = wn + ia * 8 + t4 * 2;
        #pragma unroll
        for (int hr = 0; hr < 2; ++hr) {
            const int m = m0 + wm + gid + hr * 8;
            __nv_bfloat16 p0, p1, q0, q1;
            split_bf(cc[hr * 2 + 0] * inv[hr], p0, q0);
            split_bf(cc[hr * 2 + 1] * inv[hr], p1, q1);
            const size_t o = ((size_t)(b * SEQ + m)) * EMBD + h * 64 + d;
            *(uint32_t*)(g_ph + o) = pack2(p0, p1);
            *(uint32_t*)(g_pl + o) = pack2(q0, q1);
        }
    }
}

// legacy attn-output path -------------------------------------------------
__global__ __launch_bounds__(256, 2) void scores_gemm(
    const void* __restrict__ mask, float* __restrict__ attn) {
    extern __shared__ unsigned char smem[];
    const uint32_t sb = smem_u32(smem);
    const int tid = threadIdx.x, wid = tid >> 5, lane = tid & 31;
    const int z = blockIdx.z, b = z >> 4;
    const int m0 = blockIdx.y * 128, n0 = blockIdx.x * 128;
    const size_t zo = (size_t)z * SEQ * DKH;
    #pragma unroll
    for (int s = 0; s < 2; ++s) {
        cpa(g_qh + zo + (size_t)m0 * DKH + s * 32, DKH, sb + OF_AH, s, tid);
        cpa(g_ql + zo + (size_t)m0 * DKH + s * 32, DKH, sb + OF_AL, s, tid);
        cpa(g_kh + zo + (size_t)n0 * DKH + s * 32, DKH, sb + OF_BH, s, tid);
        cpa(g_kl + zo + (size_t)n0 * DKH + s * 32, DKH, sb + OF_BL, s, tid);
    }
    CP_COMMIT(); CP_WAIT(0);
    __syncthreads();
    float acc[64] = {};
    stage_mma<128, false>(sb, 0, wid, lane, acc);
    stage_mma<128, false>(sb, 1, wid, lane, acc);
    __syncthreads();
    const int mode = g_mask_mode;
    for (int i = tid; i < 128 * 32; i += 256) {
        const int r = i >> 5, c0 = (i & 31) * 4;
        const size_t g = ((size_t)b * SEQ + m0 + r) * SEQ + n0 + c0;
        uint32_t f4;
        if (mode == 1) {
            const int4 w = *(const int4*)((const int*)mask + g);
            f4 = (w.x?1u:0u) | ((w.y?1u:0u)<<8) | ((w.z?1u:0u)<<16) | ((w.w?1u:0u)<<24);
        } else if (mode == 2) {
            const float4 w = *(const float4*)((const float*)mask + g);
            f4 = (w.x!=0.f?1u:0u) | ((w.y!=0.f?1u:0u)<<8) | ((w.z!=0.f?1u:0u)<<16) | ((w.w!=0.f?1u:0u)<<24);
        } else {
            f4 = *(const uint32_t*)((const unsigned char*)mask + g);
        }
        *(uint32_t*)(smem + OF_AH + r * 132 + c0) = f4;
    }
    __syncthreads();
    const int gid = lane >> 2, t4 = lane & 3, wm = (wid >> 1) * 32, wn = (wid & 1) * 64;
    #pragma unroll
    for (int im = 0; im < 2; ++im)
        #pragma unroll
        for (int ia = 0; ia < 8; ++ia) {
            const float* cc = acc + (im * 8 + ia) * 4;
            const int ln = wn + ia * 8 + t4 * 2;
            #pragma unroll
            for (int hr = 0; hr < 2; ++hr) {
                const int rl = wm + im * 16 + gid + hr * 8;
                const unsigned char* fr = smem + OF_AH + rl * 132 + ln;
                float2 o;
                o.x = fr[0] ? -1e9f : cc[hr * 2 + 0] * 0.125f;
                o.y = fr[1] ? -1e9f : cc[hr * 2 + 1] * 0.125f;
                *(float2*)(attn + ((size_t)z * SEQ + m0 + rl) * SEQ + n0 + ln) = o;
            }
        }
}

__global__ __launch_bounds__(256) void softmax_kernel(float* __restrict__ attn) {
    float* p = attn + (size_t)blockIdx.x * SEQ;
    const int t = threadIdx.x;
    float v[8], m = -3.4e38f;
    #pragma unroll
    for (int j = 0; j < 8; ++j) { v[j] = p[t + j * 256]; m = fmaxf(m, v[j]); }
    __shared__ float red[8]; __shared__ float bmax, bsum;
    #pragma unroll
    for (int o = 16; o > 0; o >>= 1) m = fmaxf(m, __shfl_xor_sync(0xffffffffu, m, o));
    if ((t & 31) == 0) red[t >> 5] = m;
    __syncthreads();
    if (t == 0) {
        float mm = red[0];
        #pragma unroll
        for (int i = 1; i < 8; ++i) mm = fmaxf(mm, red[i]);
        bmax = mm;
    }
    __syncthreads();
    m = bmax;
    float s = 0.f;
    #pragma unroll
    for (int j = 0; j < 8; ++j) { v[j] = __expf(v[j] - m); s += v[j]; }
    __syncthreads();
    #pragma unroll
    for (int o = 16; o > 0; o >>= 1) s += __shfl_xor_sync(0xffffffffu, s, o);
    if ((t & 31) == 0) red[t >> 5] = s;
    __syncthreads();
    if (t == 0) {
        float ss = red[0];
        #pragma unroll
        for (int i = 1; i < 8; ++i) ss += red[i];
        bsum = ss;
    }
    __syncthreads();
    const float inv = 1.0f / bsum;
    #pragma unroll
    for (int j = 0; j < 8; ++j) p[t + j * 256] = v[j] * inv;
}

__global__ __launch_bounds__(256, 2) void av_gemm(const float* __restrict__ attn) {
    extern __shared__ unsigned char smem[];
    const uint32_t sb = smem_u32(smem);
    const int tid = threadIdx.x, wid = tid >> 5, lane = tid & 31;
    const int z = blockIdx.z, b = z >> 4, h = z & 15, m0 = blockIdx.y * 128;
    const size_t zo = (size_t)z * SEQ * DKH;
    const float* Ab = attn + ((size_t)z * SEQ + m0) * SEQ;
    float4 pa[4];
    #pragma unroll
    for (int j = 0; j < 4; ++j) {
        const int i = tid + j * 256;
        pa[j] = *(const float4*)(Ab + (size_t)(i >> 3) * SEQ + (i & 7) * 4);
    }
    cpb(g_vh + zo, sb + OF_BH, 0, tid);
    cpb(g_vl + zo, sb + OF_BL, 0, tid);
    CP_COMMIT();
    __syncthreads();
    float acc[32] = {};
    for (int c = 0; c < 64; ++c) {
        const int s = c & 1;
        #pragma unroll
        for (int j = 0; j < 4; ++j) {
            const int i = tid + j * 256, r = i >> 3, q = i & 7;
            const float4 v = pa[j];
            __nv_bfloat16 h0, h1, h2, h3, l0, l1, l2, l3;
            split_bf(v.x, h0, l0); split_bf(v.y, h1, l1);
            split_bf(v.z, h2, l2); split_bf(v.w, h3, l3);
            const int cch = s * 4 + (q >> 1);
            const uint32_t ad = r * 128 + ((cch ^ (r & 7)) << 4) + (q & 1) * 8;
            *(uint2*)(smem + OF_AH + ad) = make_uint2(pack2(h0, h1), pack2(h2, h3));
            *(uint2*)(smem + OF_AL + ad) = make_uint2(pack2(l0, l1), pack2(l2, l3));
        }
        if (c < 63) {
            const int k = (c + 1) * 32, sn = (c + 1) & 1;
            #pragma unroll
            for (int j = 0; j < 4; ++j) {
                const int i = tid + j * 256;
                pa[j] = *(const float4*)(Ab + (size_t)(i >> 3) * SEQ + k + (i & 7) * 4);
            }
            cpb(g_vh + zo + (size_t)k * DKH, sb + OF_BH, sn, tid);
            cpb(g_vl + zo + (size_t)k * DKH, sb + OF_BL, sn, tid);
            CP_COMMIT(); CP_WAIT(1);
        } else CP_WAIT(0);
        __syncthreads();
        stage_mma<64, true>(sb, s, wid, lane, acc);
        __syncthreads();
    }
    const int gid = lane >> 2, t4 = lane & 3, wm = (wid >> 1) * 32, wn = (wid & 1) * 32;
    #pragma unroll
    for (int im = 0; im < 2; ++im)
        #pragma unroll
        for (int ia = 0; ia < 4; ++ia) {
            const float* cc = acc + (im * 4 + ia) * 4;
            const int d = wn + ia * 8 + t4 * 2;
            #pragma unroll
            for (int hr = 0; hr < 2; ++hr) {
                const int m = m0 + wm + im * 16 + gid + hr * 8;
                __nv_bfloat16 p0, p1, q0, q1;
                split_bf(cc[hr * 2 + 0], p0, q0);
                split_bf(cc[hr * 2 + 1], p1, q1);
                const size_t o = ((size_t)(b * SEQ + m)) * EMBD + h * 64 + d;
                *(uint32_t*)(g_ph + o) = pack2(p0, p1);
                *(uint32_t*)(g_pl + o) = pack2(q0, q1);
            }
        }
}

__global__ __launch_bounds__(256, 2) void fc_gemm(float* __restrict__ out) {
    extern __shared__ unsigned char smem[];
    const uint32_t sb = smem_u32(smem);
    const int tid = threadIdx.x, wid = tid >> 5, lane = tid & 31;
    const int m0 = blockIdx.y * 128, n0 = blockIdx.x * 128;
    const __nv_bfloat16* Ah = g_ph + (size_t)m0 * EMBD;
    const __nv_bfloat16* Al = g_pl + (size_t)m0 * EMBD;
    const __nv_bfloat16* Bh = g_wth + (size_t)3 * EMBD * EMBD + (size_t)n0 * EMBD;
    const __nv_bfloat16* Bl = g_wtl + (size_t)3 * EMBD * EMBD + (size_t)n0 * EMBD;
    float acc[64] = {};
    cpa(Ah, EMBD, sb + OF_AH, 0, tid); cpa(Al, EMBD, sb + OF_AL, 0, tid);
    cpa(Bh, EMBD, sb + OF_BH, 0, tid); cpa(Bl, EMBD, sb + OF_BL, 0, tid);
    CP_COMMIT();
    for (int c = 0; c < 32; ++c) {
        if (c < 31) {
            const int k = (c + 1) * 32, s = (c + 1) & 1;
            cpa(Ah + k, EMBD, sb + OF_AH, s, tid); cpa(Al + k, EMBD, sb + OF_AL, s, tid);
            cpa(Bh + k, EMBD, sb + OF_BH, s, tid); cpa(Bl + k, EMBD, sb + OF_BL, s, tid);
            CP_COMMIT(); CP_WAIT(1);
        } else CP_WAIT(0);
        __syncthreads();
        stage_mma<128, false>(sb, c & 1, wid, lane, acc);
        __syncthreads();
    }
    const int gid = lane >> 2, t4 = lane & 3, wm = (wid >> 1) * 32, wn = (wid & 1) * 64;
    #pragma unroll
    for (int im = 0; im < 2; ++im)
        #pragma unroll
        for (int ia = 0; ia < 8; ++ia) {
            const float* cc = acc + (im * 8 + ia) * 4;
            const int n = n0 + wn + ia * 8 + t4 * 2;
            #pragma unroll
            for (int hr = 0; hr < 2; ++hr) {
                const int m = m0 + wm + im * 16 + gid + hr * 8;
                *(float2*)(out + (size_t)m * EMBD + n) =
                    make_float2(cc[hr * 2 + 0], cc[hr * 2 + 1]);
            }
        }
}

extern "C" void kernel_launch(void* const* d_in, const int* in_sizes, int n_in,
                              void* d_out, int out_size) {
    const float* Q = (const float*)d_in[0];
    const float* K = (const float*)d_in[1];
    const float* V = (const float*)d_in[2];
    const void* mask = d_in[3];
    const float* WQ = (const float*)d_in[4];
    const float* WK = (const float*)d_in[5];
    const float* WV = (const float*)d_in[6];
    const float* Wfc = (const float*)d_in[7];
    float* out = (float*)d_out;

    const int attn_out = (out_size >= (int)(PRED_ELEMS + ATTN_ELEMS));
    float* attn_ptr;
    if (attn_out) {
        attn_ptr = out + PRED_ELEMS;
    } else {
        void* p = nullptr;
        cudaGetSymbolAddress(&p, g_attn_fb);
        attn_ptr = (float*)p;
    }

    cudaFuncSetAttribute(proj_gemm,   cudaFuncAttributeMaxDynamicSharedMemorySize, SMEM_BYTES);
    cudaFuncSetAttribute(scores_gemm, cudaFuncAttributeMaxDynamicSharedMemorySize, SMEM_BYTES);
    cudaFuncSetAttribute(av_gemm,     cudaFuncAttributeMaxDynamicSharedMemorySize, SMEM_BYTES);
    cudaFuncSetAttribute(fc_gemm,     cudaFuncAttributeMaxDynamicSharedMemorySize, SMEM_BYTES);
    cudaFuncSetAttribute(attn_fused,  cudaFuncAttributeMaxDynamicSharedMemorySize, ATT_SMEM);

    detect_mask_kernel<<<1, 1024>>>((const unsigned int*)mask);
    convert_in_kernel<<<dim3(QKV_ELEMS / 1024, 1, 3), 256>>>(Q, K, V);
    convert_w_kernel<<<dim3(32, 32, 4), 256>>>(WQ, WK, WV, Wfc);
    proj_gemm<<<dim3(8, 64, 3), 256, SMEM_BYTES>>>();
    if (attn_out) {
        scores_gemm<<<dim3(16, 16, BH), 256, SMEM_BYTES>>>(mask, attn_ptr);
        softmax_kernel<<<BH * SEQ, 256>>>(attn_ptr);
        av_gemm<<<dim3(1, 16, BH), 256, SMEM_BYTES>>>(attn_ptr);
    } else {
        attn_fused<<<dim3(16, BH), 512, ATT_SMEM>>>(mask);
    }
    fc_gemm<<<dim3(8, 64, 1), 256, SMEM_BYTES>>>(out);
}